// round 1
// baseline (speedup 1.0000x reference)
#include <cuda_runtime.h>

// ---------------- problem constants ----------------
#define BATCH 8
#define LH 16          // low-res H=W
#define HP 256         // 16*16 positions
#define HR 128         // high-res H=W
#define NOUT 4928      // hyper-net param channels

// ---------------- scratch (device globals; no allocation allowed) ----------------
__device__ float g_xcat[(size_t)BATCH * 1024 * HP];     // conv1 out (ch 0..511) + gp broadcast (512..1023)
__device__ float g_x2[(size_t)BATCH * 1024 * HP];       // conv2 out
__device__ float g_cls1T[(size_t)BATCH * HP * NOUT];    // hyper params, [b][pos][ch] (transposed for fused kernel)
__device__ float g_c1a[(size_t)BATCH * 48 * HR * HR];   // c1_bottleneck conv3x3 out

// ---------------- conv3x3 on 16x16, SAME pad, BN+ReLU ----------------
// block: 256 threads = 16x16 positions; each thread accumulates OCB out-channels.
template<int CIN, int OCB>
__global__ __launch_bounds__(256) void conv3x3_s16(
    const float* __restrict__ in, const float* __restrict__ w,
    const float* __restrict__ scale, const float* __restrict__ shift,
    float* __restrict__ out, int out_cstride)
{
    const int b = blockIdx.y, ocg = blockIdx.x, tid = threadIdx.x;
    const int ty = tid >> 4, tx = tid & 15;
    __shared__ float sIn[324];          // 18x18 padded plane
    __shared__ float sW[OCB * 9];
    float acc[OCB];
#pragma unroll
    for (int i = 0; i < OCB; i++) acc[i] = 0.f;

    const float* ip0 = in + (size_t)b * CIN * 256;
    const float* wp0 = w + (size_t)(ocg * OCB) * CIN * 9;

    for (int cin = 0; cin < CIN; ++cin) {
        const float* ip = ip0 + (size_t)cin * 256;
        for (int i = tid; i < 324; i += 256) {
            int r = i / 18, c = i - r * 18;
            int y = r - 1, x = c - 1;
            sIn[i] = ((unsigned)y < 16u && (unsigned)x < 16u) ? ip[(y << 4) + x] : 0.f;
        }
        for (int i = tid; i < OCB * 9; i += 256) {
            int oc = i / 9, k = i - oc * 9;
            sW[i] = wp0[((size_t)oc * CIN + cin) * 9 + k];
        }
        __syncthreads();
        float v[9];
#pragma unroll
        for (int ky = 0; ky < 3; ky++)
#pragma unroll
            for (int kx = 0; kx < 3; kx++)
                v[ky * 3 + kx] = sIn[(ty + ky) * 18 + (tx + kx)];
#pragma unroll
        for (int oc = 0; oc < OCB; oc++)
#pragma unroll
            for (int k = 0; k < 9; k++)
                acc[oc] = fmaf(sW[oc * 9 + k], v[k], acc[oc]);
        __syncthreads();
    }
#pragma unroll
    for (int oc = 0; oc < OCB; oc++) {
        int gc = ocg * OCB + oc;
        float r = fmaf(acc[oc], scale[gc], shift[gc]);
        r = fmaxf(r, 0.f);
        out[((size_t)b * out_cstride + gc) * 256 + tid] = r;
    }
}

// ---------------- global pooling: mean over 256 positions, broadcast into channels 512..1023 ----------------
__global__ __launch_bounds__(256) void gp_kernel()
{
    const int c = blockIdx.x, b = blockIdx.y, tid = threadIdx.x;
    size_t base = ((size_t)b * 1024 + c) * 256;
    float v = g_xcat[base + tid];
#pragma unroll
    for (int o = 16; o; o >>= 1) v += __shfl_xor_sync(0xffffffffu, v, o);
    __shared__ float red[8];
    __shared__ float meanv;
    if ((tid & 31) == 0) red[tid >> 5] = v;
    __syncthreads();
    if (tid == 0) {
        float t = 0.f;
#pragma unroll
        for (int i = 0; i < 8; i++) t += red[i];
        meanv = t * (1.f / 256.f);
    }
    __syncthreads();
    g_xcat[base + (size_t)512 * 256 + tid] = meanv;
}

// ---------------- cls1: 1x1 conv 1024 -> 4928, writes TRANSPOSED [b][pos][ch] ----------------
__global__ __launch_bounds__(256) void cls1_kernel(
    const float* __restrict__ x2, const float* __restrict__ w,
    const float* __restrict__ bias, float* __restrict__ outT)
{
    const int b = blockIdx.y, ocg = blockIdx.x, pos = threadIdx.x;
    __shared__ float sW[64 * 16];
    float acc[16];
#pragma unroll
    for (int i = 0; i < 16; i++) acc[i] = 0.f;

    for (int c0 = 0; c0 < 1024; c0 += 64) {
        for (int i = pos; i < 1024; i += 256) {
            int cc = i >> 4, oc = i & 15;
            sW[i] = w[((size_t)(ocg * 16 + oc) << 10) + c0 + cc];
        }
        __syncthreads();
#pragma unroll 8
        for (int cc = 0; cc < 64; cc++) {
            float xv = x2[(((size_t)b << 10) + (c0 + cc)) * 256 + pos];
#pragma unroll
            for (int oc = 0; oc < 16; oc++)
                acc[oc] = fmaf(sW[(cc << 4) + oc], xv, acc[oc]);
        }
        __syncthreads();
    }
    float* o = outT + ((size_t)(b * 256 + pos)) * NOUT + ocg * 16;
#pragma unroll
    for (int oc = 0; oc < 16; oc++)
        o[oc] = acc[oc] + bias[ocg * 16 + oc];
}

// ---------------- c1a: conv3x3 256->48 on 128x128, SAME, BN+ReLU ----------------
__global__ __launch_bounds__(256) void conv3x3_c1a(
    const float* __restrict__ in, const float* __restrict__ w,
    const float* __restrict__ scale, const float* __restrict__ shift,
    float* __restrict__ out)
{
    const int b = blockIdx.y, tile = blockIdx.x, tid = threadIdx.x;
    const int ty0 = (tile >> 3) << 4, tx0 = (tile & 7) << 4;
    const int ty = tid >> 4, tx = tid & 15;
    __shared__ float sIn[324];
    __shared__ float sW[48 * 9];
    float acc[48];
#pragma unroll
    for (int i = 0; i < 48; i++) acc[i] = 0.f;

    for (int cin = 0; cin < 256; ++cin) {
        const float* ip = in + (((size_t)b * 256 + cin) << 14);
        for (int i = tid; i < 324; i += 256) {
            int r = i / 18, c = i - r * 18;
            int y = ty0 - 1 + r, x = tx0 - 1 + c;
            sIn[i] = ((unsigned)y < 128u && (unsigned)x < 128u) ? ip[(y << 7) + x] : 0.f;
        }
        for (int i = tid; i < 432; i += 256) {
            int oc = i / 9, k = i - oc * 9;
            sW[i] = w[((size_t)oc * 256 + cin) * 9 + k];
        }
        __syncthreads();
        float v[9];
#pragma unroll
        for (int ky = 0; ky < 3; ky++)
#pragma unroll
            for (int kx = 0; kx < 3; kx++)
                v[ky * 3 + kx] = sIn[(ty + ky) * 18 + (tx + kx)];
#pragma unroll
        for (int oc = 0; oc < 48; oc++)
#pragma unroll
            for (int k = 0; k < 9; k++)
                acc[oc] = fmaf(sW[oc * 9 + k], v[k], acc[oc]);
        __syncthreads();
    }
#pragma unroll
    for (int oc = 0; oc < 48; oc++) {
        float r = fmaf(acc[oc], scale[oc], shift[oc]);
        r = fmaxf(r, 0.f);
        out[(((size_t)b * 48 + oc) << 14) + ((ty0 + ty) << 7) + (tx0 + tx)] = r;
    }
}

// ---------------- fused: c1b 1x1 conv + coord + cat-BN + 3-layer dynamic MLP ----------------
// block = one (b, low-res pixel). 256 threads: px = tid&63 (8x8 hi-res pixel), q = tid>>6 (quarter).
__global__ __launch_bounds__(256) void fused_final(
    const float* __restrict__ cls1T, const float* __restrict__ c1a,
    const float* __restrict__ c1b_w, const float* __restrict__ c1b_b,
    const float* __restrict__ cat_scale, const float* __restrict__ cat_shift,
    float* __restrict__ out)
{
    const int b = blockIdx.y, lpos = blockIdx.x;
    const int ly = lpos >> 4, lx = lpos & 15;
    const int tid = threadIdx.x;
    const int px = tid & 63, q = tid >> 6;
    const int py = px >> 3, pxx = px & 7;

    __shared__ float sP[NOUT];       // per-pixel hyper-net params
    __shared__ float sA[48 * 64];    // c1a patch
    __shared__ float sI[18 * 64];    // MLP input (coord + c1), BN applied
    __shared__ float sH0[16 * 64];
    __shared__ float sH1[16 * 64];
    __shared__ float sWb[768 + 16];  // c1b weights + bias

    const float* pp = cls1T + (size_t)(b * 256 + lpos) * NOUT;
    for (int i = tid; i < NOUT; i += 256) sP[i] = pp[i];
    for (int i = tid; i < 48 * 64; i += 256) {
        int ch = i >> 6, p = i & 63;
        sA[i] = c1a[(((size_t)b * 48 + ch) << 14) + ((ly * 8 + (p >> 3)) << 7) + lx * 8 + (p & 7)];
    }
    for (int i = tid; i < 768; i += 256) sWb[i] = c1b_w[i];
    if (tid < 16) sWb[768 + tid] = c1b_b[tid];
    __syncthreads();

    // c1 (16 ch) + cat-BN -> sI channels 2..17 ; coords -> channels 0,1
#pragma unroll
    for (int jj = 0; jj < 4; jj++) {
        int j = q * 4 + jj;
        float s = sWb[768 + j];
#pragma unroll
        for (int c = 0; c < 48; c++)
            s = fmaf(sA[c * 64 + px], sWb[j * 48 + c], s);
        sI[(2 + j) * 64 + px] = fmaf(s, cat_scale[2 + j], cat_shift[2 + j]);
    }
    if (q == 0) {
        sI[px]      = fmaf((float)pxx * 0.125f, cat_scale[0], cat_shift[0]);
        sI[64 + px] = fmaf((float)py  * 0.125f, cat_scale[1], cat_shift[1]);
    }
    __syncthreads();

    // stage 0: 18 -> 16, relu
#pragma unroll
    for (int jj = 0; jj < 4; jj++) {
        int o = q * 4 + jj;
        float s = sP[288 + o];
#pragma unroll
        for (int c = 0; c < 18; c++)
            s = fmaf(sP[o * 18 + c], sI[c * 64 + px], s);
        sH0[o * 64 + px] = fmaxf(s, 0.f);
    }
    __syncthreads();

    // stage 1: 16 -> 16, relu
#pragma unroll
    for (int jj = 0; jj < 4; jj++) {
        int o = q * 4 + jj;
        float s = sP[560 + o];
#pragma unroll
        for (int c = 0; c < 16; c++)
            s = fmaf(sP[304 + o * 16 + c], sH0[c * 64 + px], s);
        sH1[o * 64 + px] = fmaxf(s, 0.f);
    }
    __syncthreads();

    // stage 2: 16 -> 256, no relu; each thread does 64 outputs
    float hr[16];
#pragma unroll
    for (int c = 0; c < 16; c++) hr[c] = sH1[c * 64 + px];
    const int y = ly * 8 + py, x = lx * 8 + pxx;
    float* ob = out + (((size_t)b * 256) << 14) + (y << 7) + x;
#pragma unroll 4
    for (int oo = 0; oo < 64; oo++) {
        int o = q * 64 + oo;
        float s = sP[4672 + o];
#pragma unroll
        for (int c = 0; c < 16; c++)
            s = fmaf(sP[576 + o * 16 + c], hr[c], s);
        ob[(size_t)o << 14] = s;
    }
}

// ---------------- host launcher ----------------
extern "C" void kernel_launch(void* const* d_in, const int* in_sizes, int n_in,
                              void* d_out, int out_size)
{
    const float* res5 = (const float*)d_in[0];
    const float* res2 = (const float*)d_in[1];
    const float* bw   = (const float*)d_in[2];   // bottleneck_w [512,2048,3,3]
    const float* bn1s = (const float*)d_in[3];
    const float* bn1h = (const float*)d_in[4];
    const float* c0w  = (const float*)d_in[5];   // cls0_w [1024,1024,3,3]
    const float* bn2s = (const float*)d_in[6];
    const float* bn2h = (const float*)d_in[7];
    const float* c1w  = (const float*)d_in[8];   // cls1_w [4928,1024,1,1]
    const float* c1b  = (const float*)d_in[9];   // cls1_b [4928]
    const float* aw   = (const float*)d_in[10];  // c1a_w [48,256,3,3]
    const float* bn3s = (const float*)d_in[11];
    const float* bn3h = (const float*)d_in[12];
    const float* bw2  = (const float*)d_in[13];  // c1b_w [16,48,1,1]
    const float* bb2  = (const float*)d_in[14];  // c1b_b [16]
    const float* cats = (const float*)d_in[15];  // cat_scale [18]
    const float* cath = (const float*)d_in[16];  // cat_shift [18]
    float* out = (float*)d_out;

    float *xcat, *x2, *cls1T, *c1a;
    cudaGetSymbolAddress((void**)&xcat,  g_xcat);
    cudaGetSymbolAddress((void**)&x2,    g_x2);
    cudaGetSymbolAddress((void**)&cls1T, g_cls1T);
    cudaGetSymbolAddress((void**)&c1a,   g_c1a);

    // bottleneck conv: res5 [8,2048,16,16] -> g_xcat ch 0..511 (BN+ReLU)
    conv3x3_s16<2048, 16><<<dim3(32, BATCH), 256>>>(res5, bw, bn1s, bn1h, xcat, 1024);
    // global pool broadcast into ch 512..1023
    gp_kernel<<<dim3(512, BATCH), 256>>>();
    // classifier conv0: g_xcat [8,1024,16,16] -> g_x2 (BN+ReLU)
    conv3x3_s16<1024, 16><<<dim3(64, BATCH), 256>>>(xcat, c0w, bn2s, bn2h, x2, 1024);
    // classifier conv1 (1x1): g_x2 -> g_cls1T [b][pos][4928]
    cls1_kernel<<<dim3(NOUT / 16, BATCH), 256>>>(x2, c1w, c1b, cls1T);
    // c1 bottleneck conv3x3: res2 -> g_c1a (BN+ReLU)
    conv3x3_c1a<<<dim3(64, BATCH), 256>>>(res2, aw, bn3s, bn3h, c1a);
    // fused c1b + coord + cat-BN + dynamic MLP -> out
    fused_final<<<dim3(256, BATCH), 256>>>(cls1T, c1a, bw2, bb2, cats, cath, out);
}

// round 2
// speedup vs baseline: 1.0017x; 1.0017x over previous
#include <cuda_runtime.h>

// ---------------- problem constants ----------------
#define BATCH 8
#define HP 256         // 16*16 positions
#define HR 128         // high-res H=W
#define NOUT 4928      // hyper-net param channels

typedef unsigned long long ull;

// ---------------- packed fp32 helpers ----------------
__device__ __forceinline__ ull pack2(float lo, float hi) {
    ull r; asm("mov.b64 %0, {%1, %2};" : "=l"(r) : "f"(lo), "f"(hi)); return r;
}
__device__ __forceinline__ void unpack2(ull v, float& lo, float& hi) {
    asm("mov.b64 {%0, %1}, %2;" : "=f"(lo), "=f"(hi) : "l"(v));
}
__device__ __forceinline__ ull fma2(ull a, ull b, ull c) {
    ull d; asm("fma.rn.f32x2 %0, %1, %2, %3;" : "=l"(d) : "l"(a), "l"(b), "l"(c)); return d;
}

// ---------------- scratch ----------------
__device__ float g_xcat[(size_t)BATCH * 1024 * HP];
__device__ float g_x2[(size_t)BATCH * 1024 * HP];
__device__ float g_cls1T[(size_t)BATCH * HP * NOUT];
__device__ float g_c1a[(size_t)BATCH * 48 * HR * HR];

// =====================================================================
// conv3x3 on 16x16, SAME, BN+ReLU.  Block: 256 thr = 4 cin-quarters x
// 64 spatial threads (each owns a 2x2 output patch). Block computes 16 oc.
// Inner math: f32x2 packed over horizontal position pairs; weights stored
// duplicated in shared so one LDS.64 = packed broadcast operand.
// =====================================================================
template<int CIN>
__global__ __launch_bounds__(256) void conv3x3_v2(
    const float* __restrict__ in, const float* __restrict__ w,
    const float* __restrict__ scale, const float* __restrict__ shift,
    float* __restrict__ out, int out_cstride)
{
    constexpr int CINQ = CIN / 4;
    const int b = blockIdx.y, ocg = blockIdx.x, tid = threadIdx.x;
    const int q = tid >> 6, s = tid & 63;
    const int py0 = (s >> 3) << 1, px0 = (s & 7) << 1;

    __shared__ __align__(16) char smem[19584];
    float* sIn = (float*)smem;            // [4 quarters][2 cin][324]
    ull*   sW  = (ull*)(smem + 10368);    // [4 quarters][2 cin][144]

    ull accA[16], accB[16];
#pragma unroll
    for (int i = 0; i < 16; i++) { accA[i] = 0ull; accB[i] = 0ull; }

    const float* ip0 = in + ((size_t)b * CIN + q * CINQ) * 256;
    const int ocbase = ocg * 16;

    for (int c0 = 0; c0 < CINQ; c0 += 2) {
        // load 2 input planes for this quarter's cin
        for (int i = s; i < 648; i += 64) {
            int cc = (i >= 324) ? 1 : 0, j = i - cc * 324;
            int r = j / 18, c = j - r * 18;
            int y = r - 1, x = c - 1;
            float v = 0.f;
            if ((unsigned)y < 16u && (unsigned)x < 16u)
                v = ip0[((size_t)(c0 + cc) << 8) + (y << 4) + x];
            sIn[q * 648 + i] = v;
        }
        // load + duplicate weights
        for (int i = s; i < 288; i += 64) {
            int cc = (i >= 144) ? 1 : 0, j = i - cc * 144;
            int oc = j / 9, k = j - oc * 9;
            float wv = w[((size_t)(ocbase + oc) * CIN + q * CINQ + c0 + cc) * 9 + k];
            sW[q * 288 + i] = pack2(wv, wv);
        }
        __syncthreads();
#pragma unroll
        for (int cc = 0; cc < 2; cc++) {
            const float* P = sIn + q * 648 + cc * 324;
            float xv[4][4];
#pragma unroll
            for (int r = 0; r < 4; r++)
#pragma unroll
                for (int c = 0; c < 4; c++)
                    xv[r][c] = P[(py0 + r) * 18 + px0 + c];
            ull pr[4][3];
#pragma unroll
            for (int r = 0; r < 4; r++)
#pragma unroll
                for (int j = 0; j < 3; j++)
                    pr[r][j] = pack2(xv[r][j], xv[r][j + 1]);
            const ull* W = sW + q * 288 + cc * 144;
#pragma unroll
            for (int oc = 0; oc < 16; oc++) {
#pragma unroll
                for (int ky = 0; ky < 3; ky++)
#pragma unroll
                    for (int kx = 0; kx < 3; kx++) {
                        ull w64 = W[oc * 9 + ky * 3 + kx];
                        accA[oc] = fma2(pr[ky][kx], w64, accA[oc]);
                        accB[oc] = fma2(pr[ky + 1][kx], w64, accB[oc]);
                    }
            }
        }
        __syncthreads();
    }

    // reduce 4 cin-quarters through shared
    float* sRed = (float*)smem;   // [16 oc][256 pos]
    for (int qq = 0; qq < 4; qq++) {
        if (q == qq) {
#pragma unroll
            for (int oc = 0; oc < 16; oc++) {
                float a0, a1, b0, b1;
                unpack2(accA[oc], a0, a1);
                unpack2(accB[oc], b0, b1);
                int p = py0 * 16 + px0;
                if (qq == 0) {
                    sRed[oc * 256 + p] = a0;       sRed[oc * 256 + p + 1] = a1;
                    sRed[oc * 256 + p + 16] = b0;  sRed[oc * 256 + p + 17] = b1;
                } else {
                    sRed[oc * 256 + p] += a0;      sRed[oc * 256 + p + 1] += a1;
                    sRed[oc * 256 + p + 16] += b0; sRed[oc * 256 + p + 17] += b1;
                }
            }
        }
        __syncthreads();
    }
    for (int i = tid; i < 4096; i += 256) {
        int oc = i >> 8, pos = i & 255;
        int gc = ocbase + oc;
        float r = fmaf(sRed[i], scale[gc], shift[gc]);
        out[((size_t)b * out_cstride + gc) * 256 + pos] = fmaxf(r, 0.f);
    }
}

// ---------------- global pooling broadcast ----------------
__global__ __launch_bounds__(256) void gp_kernel()
{
    const int c = blockIdx.x, b = blockIdx.y, tid = threadIdx.x;
    size_t base = ((size_t)b * 1024 + c) * 256;
    float v = g_xcat[base + tid];
#pragma unroll
    for (int o = 16; o; o >>= 1) v += __shfl_xor_sync(0xffffffffu, v, o);
    __shared__ float red[8];
    __shared__ float meanv;
    if ((tid & 31) == 0) red[tid >> 5] = v;
    __syncthreads();
    if (tid == 0) {
        float t = 0.f;
#pragma unroll
        for (int i = 0; i < 8; i++) t += red[i];
        meanv = t * (1.f / 256.f);
    }
    __syncthreads();
    g_xcat[base + (size_t)512 * 256 + tid] = meanv;
}

// =====================================================================
// cls1: 1x1 conv 1024 -> 4928 as packed GEMM, writes [b][pos][ch].
// Block 256 thr = 8 oc-groups x 32 pos-threads. Each thread: 4 position
// pairs (8 consecutive pos, natural LDS.64) x 8 oc.  Block oc = 64.
// =====================================================================
__global__ __launch_bounds__(256) void cls1_v2(
    const float* __restrict__ x2, const float* __restrict__ w,
    const float* __restrict__ bias, float* __restrict__ outT)
{
    const int b = blockIdx.y, ocb = blockIdx.x * 64, tid = threadIdx.x;
    const int og = tid >> 5, sp = tid & 31;

    __shared__ __align__(16) char smem[24576];
    float* sX = (float*)smem;            // [16 cin][256 pos]
    ull*   sW = (ull*)(smem + 16384);    // [16 cin][64 oc] duplicated

    ull acc[8][4];
#pragma unroll
    for (int i = 0; i < 8; i++)
#pragma unroll
        for (int j = 0; j < 4; j++) acc[i][j] = 0ull;

    for (int c0 = 0; c0 < 1024; c0 += 16) {
        for (int i = tid; i < 4096; i += 256) {
            int cc = i >> 8, p = i & 255;
            sX[i] = x2[(((size_t)b << 10) + (c0 + cc)) * 256 + p];
        }
        for (int i = tid; i < 1024; i += 256) {
            int cc = i >> 6, oc = i & 63;
            float wv = w[(size_t)(ocb + oc) * 1024 + c0 + cc];
            sW[i] = pack2(wv, wv);
        }
        __syncthreads();
#pragma unroll
        for (int cc = 0; cc < 16; cc++) {
            const ull* xr = (const ull*)(sX + cc * 256) + sp * 4;
            ull xp[4];
#pragma unroll
            for (int j = 0; j < 4; j++) xp[j] = xr[j];
#pragma unroll
            for (int oc = 0; oc < 8; oc++) {
                ull w64 = sW[cc * 64 + og * 8 + oc];
#pragma unroll
                for (int j = 0; j < 4; j++) acc[oc][j] = fma2(xp[j], w64, acc[oc][j]);
            }
        }
        __syncthreads();
    }
#pragma unroll
    for (int oc = 0; oc < 8; oc++) {
        int gc = ocb + og * 8 + oc;
        float bv = bias[gc];
#pragma unroll
        for (int j = 0; j < 4; j++) {
            float a0, a1;
            unpack2(acc[oc][j], a0, a1);
            int pos = sp * 8 + 2 * j;
            float* o = outT + ((size_t)(b * 256 + pos)) * NOUT + gc;
            o[0] = a0 + bv;
            o[NOUT] = a1 + bv;
        }
    }
}

// =====================================================================
// c1a: conv3x3 256->48 on 128x128, SAME, BN+ReLU.
// Block 256 thr = 4 oc-groups (12 oc each) x 64 spatial threads (2x2
// patch in a 16x16 tile). All groups share the input plane.
// =====================================================================
__global__ __launch_bounds__(256) void c1a_v2(
    const float* __restrict__ in, const float* __restrict__ w,
    const float* __restrict__ scale, const float* __restrict__ shift,
    float* __restrict__ out)
{
    const int b = blockIdx.y, tile = blockIdx.x, tid = threadIdx.x;
    const int ty0 = (tile >> 3) << 4, tx0 = (tile & 7) << 4;
    const int og = tid >> 6, s = tid & 63;
    const int py0 = (s >> 3) << 1, px0 = (s & 7) << 1;

    __shared__ __align__(16) char smem[9504];
    float* sIn = (float*)smem;            // [2 cin][324]
    ull*   sW  = (ull*)(smem + 2592);     // [2 cin][48*9] duplicated

    ull accA[12], accB[12];
#pragma unroll
    for (int i = 0; i < 12; i++) { accA[i] = 0ull; accB[i] = 0ull; }

    for (int c0 = 0; c0 < 256; c0 += 2) {
        for (int i = tid; i < 648; i += 256) {
            int cc = (i >= 324) ? 1 : 0, j = i - cc * 324;
            int r = j / 18, c = j - r * 18;
            int y = ty0 - 1 + r, x = tx0 - 1 + c;
            float v = 0.f;
            if ((unsigned)y < 128u && (unsigned)x < 128u)
                v = in[(((size_t)b * 256 + c0 + cc) << 14) + (y << 7) + x];
            sIn[i] = v;
        }
        for (int i = tid; i < 864; i += 256) {
            int cc = (i >= 432) ? 1 : 0, j = i - cc * 432;
            int oc = j / 9, k = j - oc * 9;
            float wv = w[((size_t)oc * 256 + c0 + cc) * 9 + k];
            sW[i] = pack2(wv, wv);
        }
        __syncthreads();
#pragma unroll
        for (int cc = 0; cc < 2; cc++) {
            const float* P = sIn + cc * 324;
            float xv[4][4];
#pragma unroll
            for (int r = 0; r < 4; r++)
#pragma unroll
                for (int c = 0; c < 4; c++)
                    xv[r][c] = P[(py0 + r) * 18 + px0 + c];
            ull pr[4][3];
#pragma unroll
            for (int r = 0; r < 4; r++)
#pragma unroll
                for (int j = 0; j < 3; j++)
                    pr[r][j] = pack2(xv[r][j], xv[r][j + 1]);
            const ull* W = sW + cc * 432 + og * 108;
#pragma unroll
            for (int oc = 0; oc < 12; oc++) {
#pragma unroll
                for (int ky = 0; ky < 3; ky++)
#pragma unroll
                    for (int kx = 0; kx < 3; kx++) {
                        ull w64 = W[oc * 9 + ky * 3 + kx];
                        accA[oc] = fma2(pr[ky][kx], w64, accA[oc]);
                        accB[oc] = fma2(pr[ky + 1][kx], w64, accB[oc]);
                    }
            }
        }
        __syncthreads();
    }
#pragma unroll
    for (int oc = 0; oc < 12; oc++) {
        int gc = og * 12 + oc;
        float sc = scale[gc], sh = shift[gc];
        float a0, a1, b0, b1;
        unpack2(accA[oc], a0, a1);
        unpack2(accB[oc], b0, b1);
        int y = ty0 + py0, x = tx0 + px0;
        float* ob = out + (((size_t)b * 48 + gc) << 14) + (y << 7) + x;
        ob[0]   = fmaxf(fmaf(a0, sc, sh), 0.f);
        ob[1]   = fmaxf(fmaf(a1, sc, sh), 0.f);
        ob[128] = fmaxf(fmaf(b0, sc, sh), 0.f);
        ob[129] = fmaxf(fmaf(b1, sc, sh), 0.f);
    }
}

// ---------------- fused: c1b + coord + cat-BN + dynamic MLP ----------------
__global__ __launch_bounds__(256) void fused_final(
    const float* __restrict__ cls1T, const float* __restrict__ c1a,
    const float* __restrict__ c1b_w, const float* __restrict__ c1b_b,
    const float* __restrict__ cat_scale, const float* __restrict__ cat_shift,
    float* __restrict__ out)
{
    const int b = blockIdx.y, lpos = blockIdx.x;
    const int ly = lpos >> 4, lx = lpos & 15;
    const int tid = threadIdx.x;
    const int px = tid & 63, q = tid >> 6;
    const int py = px >> 3, pxx = px & 7;

    __shared__ float sP[NOUT];
    __shared__ float sA[48 * 64];
    __shared__ float sI[18 * 64];
    __shared__ float sH0[16 * 64];
    __shared__ float sH1[16 * 64];
    __shared__ float sWb[768 + 16];

    const float* pp = cls1T + (size_t)(b * 256 + lpos) * NOUT;
    for (int i = tid; i < NOUT; i += 256) sP[i] = pp[i];
    for (int i = tid; i < 48 * 64; i += 256) {
        int ch = i >> 6, p = i & 63;
        sA[i] = c1a[(((size_t)b * 48 + ch) << 14) + ((ly * 8 + (p >> 3)) << 7) + lx * 8 + (p & 7)];
    }
    for (int i = tid; i < 768; i += 256) sWb[i] = c1b_w[i];
    if (tid < 16) sWb[768 + tid] = c1b_b[tid];
    __syncthreads();

#pragma unroll
    for (int jj = 0; jj < 4; jj++) {
        int j = q * 4 + jj;
        float s = sWb[768 + j];
#pragma unroll
        for (int c = 0; c < 48; c++)
            s = fmaf(sA[c * 64 + px], sWb[j * 48 + c], s);
        sI[(2 + j) * 64 + px] = fmaf(s, cat_scale[2 + j], cat_shift[2 + j]);
    }
    if (q == 0) {
        sI[px]      = fmaf((float)pxx * 0.125f, cat_scale[0], cat_shift[0]);
        sI[64 + px] = fmaf((float)py  * 0.125f, cat_scale[1], cat_shift[1]);
    }
    __syncthreads();

#pragma unroll
    for (int jj = 0; jj < 4; jj++) {
        int o = q * 4 + jj;
        float s = sP[288 + o];
#pragma unroll
        for (int c = 0; c < 18; c++)
            s = fmaf(sP[o * 18 + c], sI[c * 64 + px], s);
        sH0[o * 64 + px] = fmaxf(s, 0.f);
    }
    __syncthreads();

#pragma unroll
    for (int jj = 0; jj < 4; jj++) {
        int o = q * 4 + jj;
        float s = sP[560 + o];
#pragma unroll
        for (int c = 0; c < 16; c++)
            s = fmaf(sP[304 + o * 16 + c], sH0[c * 64 + px], s);
        sH1[o * 64 + px] = fmaxf(s, 0.f);
    }
    __syncthreads();

    float hr[16];
#pragma unroll
    for (int c = 0; c < 16; c++) hr[c] = sH1[c * 64 + px];
    const int y = ly * 8 + py, x = lx * 8 + pxx;
    float* ob = out + (((size_t)b * 256) << 14) + (y << 7) + x;
#pragma unroll 4
    for (int oo = 0; oo < 64; oo++) {
        int o = q * 64 + oo;
        float s = sP[4672 + o];
#pragma unroll
        for (int c = 0; c < 16; c++)
            s = fmaf(sP[576 + o * 16 + c], hr[c], s);
        ob[(size_t)o << 14] = s;
    }
}

// ---------------- host launcher ----------------
extern "C" void kernel_launch(void* const* d_in, const int* in_sizes, int n_in,
                              void* d_out, int out_size)
{
    const float* res5 = (const float*)d_in[0];
    const float* res2 = (const float*)d_in[1];
    const float* bw   = (const float*)d_in[2];
    const float* bn1s = (const float*)d_in[3];
    const float* bn1h = (const float*)d_in[4];
    const float* c0w  = (const float*)d_in[5];
    const float* bn2s = (const float*)d_in[6];
    const float* bn2h = (const float*)d_in[7];
    const float* c1w  = (const float*)d_in[8];
    const float* c1b  = (const float*)d_in[9];
    const float* aw   = (const float*)d_in[10];
    const float* bn3s = (const float*)d_in[11];
    const float* bn3h = (const float*)d_in[12];
    const float* bw2  = (const float*)d_in[13];
    const float* bb2  = (const float*)d_in[14];
    const float* cats = (const float*)d_in[15];
    const float* cath = (const float*)d_in[16];
    float* out = (float*)d_out;

    float *xcat, *x2, *cls1T, *c1a;
    cudaGetSymbolAddress((void**)&xcat,  g_xcat);
    cudaGetSymbolAddress((void**)&x2,    g_x2);
    cudaGetSymbolAddress((void**)&cls1T, g_cls1T);
    cudaGetSymbolAddress((void**)&c1a,   g_c1a);

    conv3x3_v2<2048><<<dim3(32, BATCH), 256>>>(res5, bw, bn1s, bn1h, xcat, 1024);
    gp_kernel<<<dim3(512, BATCH), 256>>>();
    conv3x3_v2<1024><<<dim3(64, BATCH), 256>>>(xcat, c0w, bn2s, bn2h, x2, 1024);
    cls1_v2<<<dim3(77, BATCH), 256>>>(x2, c1w, c1b, cls1T);
    c1a_v2<<<dim3(64, BATCH), 256>>>(res2, aw, bn3s, bn3h, c1a);
    fused_final<<<dim3(256, BATCH), 256>>>(cls1T, c1a, bw2, bb2, cats, cath, out);
}

// round 3
// speedup vs baseline: 1.0040x; 1.0023x over previous
#include <cuda_runtime.h>

// ---------------- problem constants ----------------
#define BATCH 8
#define HP 256         // 16*16 positions
#define HR 128         // high-res H=W
#define NOUT 4928      // hyper-net param channels

typedef unsigned long long ull;

// ---------------- packed fp32 helpers ----------------
__device__ __forceinline__ ull pack2(float lo, float hi) {
    ull r; asm("mov.b64 %0, {%1, %2};" : "=l"(r) : "f"(lo), "f"(hi)); return r;
}
__device__ __forceinline__ void unpack2(ull v, float& lo, float& hi) {
    asm("mov.b64 {%0, %1}, %2;" : "=f"(lo), "=f"(hi) : "l"(v));
}
__device__ __forceinline__ ull fma2(ull a, ull b, ull c) {
    ull d; asm("fma.rn.f32x2 %0, %1, %2, %3;" : "=l"(d) : "l"(a), "l"(b), "l"(c)); return d;
}

// ---------------- scratch ----------------
__device__ float g_xcat[(size_t)BATCH * 1024 * HP];
__device__ float g_x2[(size_t)BATCH * 1024 * HP];
__device__ float g_cls1T[(size_t)BATCH * HP * NOUT];
__device__ float g_c1a[(size_t)BATCH * 48 * HR * HR];

// =====================================================================
// conv3x3 on 16x16, SAME, BN+ReLU.  Block: 256 thr = 4 cin-quarters x
// 64 spatial threads (each owns a 2x2 output patch). Block computes 16 oc.
// Inner math: f32x2 packed over horizontal position pairs; weights stored
// duplicated in shared so one LDS.64 = packed broadcast operand.
// =====================================================================
template<int CIN>
__global__ __launch_bounds__(256) void conv3x3_v2(
    const float* __restrict__ in, const float* __restrict__ w,
    const float* __restrict__ scale, const float* __restrict__ shift,
    float* __restrict__ out, int out_cstride)
{
    constexpr int CINQ = CIN / 4;
    const int b = blockIdx.y, ocg = blockIdx.x, tid = threadIdx.x;
    const int q = tid >> 6, s = tid & 63;
    const int py0 = (s >> 3) << 1, px0 = (s & 7) << 1;

    __shared__ __align__(16) char smem[19584];
    float* sIn = (float*)smem;            // [4 quarters][2 cin][324]
    ull*   sW  = (ull*)(smem + 10368);    // [4 quarters][2 cin][144]

    ull accA[16], accB[16];
#pragma unroll
    for (int i = 0; i < 16; i++) { accA[i] = 0ull; accB[i] = 0ull; }

    const float* ip0 = in + ((size_t)b * CIN + q * CINQ) * 256;
    const int ocbase = ocg * 16;

    for (int c0 = 0; c0 < CINQ; c0 += 2) {
        // load 2 input planes for this quarter's cin
        for (int i = s; i < 648; i += 64) {
            int cc = (i >= 324) ? 1 : 0, j = i - cc * 324;
            int r = j / 18, c = j - r * 18;
            int y = r - 1, x = c - 1;
            float v = 0.f;
            if ((unsigned)y < 16u && (unsigned)x < 16u)
                v = ip0[((size_t)(c0 + cc) << 8) + (y << 4) + x];
            sIn[q * 648 + i] = v;
        }
        // load + duplicate weights
        for (int i = s; i < 288; i += 64) {
            int cc = (i >= 144) ? 1 : 0, j = i - cc * 144;
            int oc = j / 9, k = j - oc * 9;
            float wv = w[((size_t)(ocbase + oc) * CIN + q * CINQ + c0 + cc) * 9 + k];
            sW[q * 288 + i] = pack2(wv, wv);
        }
        __syncthreads();
#pragma unroll
        for (int cc = 0; cc < 2; cc++) {
            const float* P = sIn + q * 648 + cc * 324;
            float xv[4][4];
#pragma unroll
            for (int r = 0; r < 4; r++)
#pragma unroll
                for (int c = 0; c < 4; c++)
                    xv[r][c] = P[(py0 + r) * 18 + px0 + c];
            ull pr[4][3];
#pragma unroll
            for (int r = 0; r < 4; r++)
#pragma unroll
                for (int j = 0; j < 3; j++)
                    pr[r][j] = pack2(xv[r][j], xv[r][j + 1]);
            const ull* W = sW + q * 288 + cc * 144;
#pragma unroll
            for (int oc = 0; oc < 16; oc++) {
#pragma unroll
                for (int ky = 0; ky < 3; ky++)
#pragma unroll
                    for (int kx = 0; kx < 3; kx++) {
                        ull w64 = W[oc * 9 + ky * 3 + kx];
                        accA[oc] = fma2(pr[ky][kx], w64, accA[oc]);
                        accB[oc] = fma2(pr[ky + 1][kx], w64, accB[oc]);
                    }
            }
        }
        __syncthreads();
    }

    // reduce 4 cin-quarters through shared
    float* sRed = (float*)smem;   // [16 oc][256 pos]
    for (int qq = 0; qq < 4; qq++) {
        if (q == qq) {
#pragma unroll
            for (int oc = 0; oc < 16; oc++) {
                float a0, a1, b0, b1;
                unpack2(accA[oc], a0, a1);
                unpack2(accB[oc], b0, b1);
                int p = py0 * 16 + px0;
                if (qq == 0) {
                    sRed[oc * 256 + p] = a0;       sRed[oc * 256 + p + 1] = a1;
                    sRed[oc * 256 + p + 16] = b0;  sRed[oc * 256 + p + 17] = b1;
                } else {
                    sRed[oc * 256 + p] += a0;      sRed[oc * 256 + p + 1] += a1;
                    sRed[oc * 256 + p + 16] += b0; sRed[oc * 256 + p + 17] += b1;
                }
            }
        }
        __syncthreads();
    }
    for (int i = tid; i < 4096; i += 256) {
        int oc = i >> 8, pos = i & 255;
        int gc = ocbase + oc;
        float r = fmaf(sRed[i], scale[gc], shift[gc]);
        out[((size_t)b * out_cstride + gc) * 256 + pos] = fmaxf(r, 0.f);
    }
}

// ---------------- global pooling broadcast ----------------
__global__ __launch_bounds__(256) void gp_kernel()
{
    const int c = blockIdx.x, b = blockIdx.y, tid = threadIdx.x;
    size_t base = ((size_t)b * 1024 + c) * 256;
    float v = g_xcat[base + tid];
#pragma unroll
    for (int o = 16; o; o >>= 1) v += __shfl_xor_sync(0xffffffffu, v, o);
    __shared__ float red[8];
    __shared__ float meanv;
    if ((tid & 31) == 0) red[tid >> 5] = v;
    __syncthreads();
    if (tid == 0) {
        float t = 0.f;
#pragma unroll
        for (int i = 0; i < 8; i++) t += red[i];
        meanv = t * (1.f / 256.f);
    }
    __syncthreads();
    g_xcat[base + (size_t)512 * 256 + tid] = meanv;
}

// =====================================================================
// cls1: 1x1 conv 1024 -> 4928 as packed GEMM, writes [b][pos][ch].
// Block 256 thr = 8 oc-groups x 32 pos-threads. Each thread: 4 position
// pairs (8 consecutive pos, natural LDS.64) x 8 oc.  Block oc = 64.
// =====================================================================
__global__ __launch_bounds__(256) void cls1_v2(
    const float* __restrict__ x2, const float* __restrict__ w,
    const float* __restrict__ bias, float* __restrict__ outT)
{
    const int b = blockIdx.y, ocb = blockIdx.x * 64, tid = threadIdx.x;
    const int og = tid >> 5, sp = tid & 31;

    __shared__ __align__(16) char smem[24576];
    float* sX = (float*)smem;            // [16 cin][256 pos]
    ull*   sW = (ull*)(smem + 16384);    // [16 cin][64 oc] duplicated

    ull acc[8][4];
#pragma unroll
    for (int i = 0; i < 8; i++)
#pragma unroll
        for (int j = 0; j < 4; j++) acc[i][j] = 0ull;

    for (int c0 = 0; c0 < 1024; c0 += 16) {
        for (int i = tid; i < 4096; i += 256) {
            int cc = i >> 8, p = i & 255;
            sX[i] = x2[(((size_t)b << 10) + (c0 + cc)) * 256 + p];
        }
        for (int i = tid; i < 1024; i += 256) {
            int cc = i >> 6, oc = i & 63;
            float wv = w[(size_t)(ocb + oc) * 1024 + c0 + cc];
            sW[i] = pack2(wv, wv);
        }
        __syncthreads();
#pragma unroll
        for (int cc = 0; cc < 16; cc++) {
            const ull* xr = (const ull*)(sX + cc * 256) + sp * 4;
            ull xp[4];
#pragma unroll
            for (int j = 0; j < 4; j++) xp[j] = xr[j];
#pragma unroll
            for (int oc = 0; oc < 8; oc++) {
                ull w64 = sW[cc * 64 + og * 8 + oc];
#pragma unroll
                for (int j = 0; j < 4; j++) acc[oc][j] = fma2(xp[j], w64, acc[oc][j]);
            }
        }
        __syncthreads();
    }
#pragma unroll
    for (int oc = 0; oc < 8; oc++) {
        int gc = ocb + og * 8 + oc;
        float bv = bias[gc];
#pragma unroll
        for (int j = 0; j < 4; j++) {
            float a0, a1;
            unpack2(acc[oc][j], a0, a1);
            int pos = sp * 8 + 2 * j;
            float* o = outT + ((size_t)(b * 256 + pos)) * NOUT + gc;
            o[0] = a0 + bv;
            o[NOUT] = a1 + bv;
        }
    }
}

// =====================================================================
// c1a: conv3x3 256->48 on 128x128, SAME, BN+ReLU.
// Block 256 thr = 4 oc-groups (12 oc each) x 64 spatial threads (2x2
// patch in a 16x16 tile). All groups share the input plane.
// =====================================================================
__global__ __launch_bounds__(256) void c1a_v2(
    const float* __restrict__ in, const float* __restrict__ w,
    const float* __restrict__ scale, const float* __restrict__ shift,
    float* __restrict__ out)
{
    const int b = blockIdx.y, tile = blockIdx.x, tid = threadIdx.x;
    const int ty0 = (tile >> 3) << 4, tx0 = (tile & 7) << 4;
    const int og = tid >> 6, s = tid & 63;
    const int py0 = (s >> 3) << 1, px0 = (s & 7) << 1;

    __shared__ __align__(16) char smem[9504];
    float* sIn = (float*)smem;            // [2 cin][324]
    ull*   sW  = (ull*)(smem + 2592);     // [2 cin][48*9] duplicated

    ull accA[12], accB[12];
#pragma unroll
    for (int i = 0; i < 12; i++) { accA[i] = 0ull; accB[i] = 0ull; }

    for (int c0 = 0; c0 < 256; c0 += 2) {
        for (int i = tid; i < 648; i += 256) {
            int cc = (i >= 324) ? 1 : 0, j = i - cc * 324;
            int r = j / 18, c = j - r * 18;
            int y = ty0 - 1 + r, x = tx0 - 1 + c;
            float v = 0.f;
            if ((unsigned)y < 128u && (unsigned)x < 128u)
                v = in[(((size_t)b * 256 + c0 + cc) << 14) + (y << 7) + x];
            sIn[i] = v;
        }
        for (int i = tid; i < 864; i += 256) {
            int cc = (i >= 432) ? 1 : 0, j = i - cc * 432;
            int oc = j / 9, k = j - oc * 9;
            float wv = w[((size_t)oc * 256 + c0 + cc) * 9 + k];
            sW[i] = pack2(wv, wv);
        }
        __syncthreads();
#pragma unroll
        for (int cc = 0; cc < 2; cc++) {
            const float* P = sIn + cc * 324;
            float xv[4][4];
#pragma unroll
            for (int r = 0; r < 4; r++)
#pragma unroll
                for (int c = 0; c < 4; c++)
                    xv[r][c] = P[(py0 + r) * 18 + px0 + c];
            ull pr[4][3];
#pragma unroll
            for (int r = 0; r < 4; r++)
#pragma unroll
                for (int j = 0; j < 3; j++)
                    pr[r][j] = pack2(xv[r][j], xv[r][j + 1]);
            const ull* W = sW + cc * 432 + og * 108;
#pragma unroll
            for (int oc = 0; oc < 12; oc++) {
#pragma unroll
                for (int ky = 0; ky < 3; ky++)
#pragma unroll
                    for (int kx = 0; kx < 3; kx++) {
                        ull w64 = W[oc * 9 + ky * 3 + kx];
                        accA[oc] = fma2(pr[ky][kx], w64, accA[oc]);
                        accB[oc] = fma2(pr[ky + 1][kx], w64, accB[oc]);
                    }
            }
        }
        __syncthreads();
    }
#pragma unroll
    for (int oc = 0; oc < 12; oc++) {
        int gc = og * 12 + oc;
        float sc = scale[gc], sh = shift[gc];
        float a0, a1, b0, b1;
        unpack2(accA[oc], a0, a1);
        unpack2(accB[oc], b0, b1);
        int y = ty0 + py0, x = tx0 + px0;
        float* ob = out + (((size_t)b * 48 + gc) << 14) + (y << 7) + x;
        ob[0]   = fmaxf(fmaf(a0, sc, sh), 0.f);
        ob[1]   = fmaxf(fmaf(a1, sc, sh), 0.f);
        ob[128] = fmaxf(fmaf(b0, sc, sh), 0.f);
        ob[129] = fmaxf(fmaf(b1, sc, sh), 0.f);
    }
}

// ---------------- fused: c1b + coord + cat-BN + dynamic MLP ----------------
__global__ __launch_bounds__(256) void fused_final(
    const float* __restrict__ cls1T, const float* __restrict__ c1a,
    const float* __restrict__ c1b_w, const float* __restrict__ c1b_b,
    const float* __restrict__ cat_scale, const float* __restrict__ cat_shift,
    float* __restrict__ out)
{
    const int b = blockIdx.y, lpos = blockIdx.x;
    const int ly = lpos >> 4, lx = lpos & 15;
    const int tid = threadIdx.x;
    const int px = tid & 63, q = tid >> 6;
    const int py = px >> 3, pxx = px & 7;

    __shared__ float sP[NOUT];
    __shared__ float sA[48 * 64];
    __shared__ float sI[18 * 64];
    __shared__ float sH0[16 * 64];
    __shared__ float sH1[16 * 64];
    __shared__ float sWb[768 + 16];

    const float* pp = cls1T + (size_t)(b * 256 + lpos) * NOUT;
    for (int i = tid; i < NOUT; i += 256) sP[i] = pp[i];
    for (int i = tid; i < 48 * 64; i += 256) {
        int ch = i >> 6, p = i & 63;
        sA[i] = c1a[(((size_t)b * 48 + ch) << 14) + ((ly * 8 + (p >> 3)) << 7) + lx * 8 + (p & 7)];
    }
    for (int i = tid; i < 768; i += 256) sWb[i] = c1b_w[i];
    if (tid < 16) sWb[768 + tid] = c1b_b[tid];
    __syncthreads();

#pragma unroll
    for (int jj = 0; jj < 4; jj++) {
        int j = q * 4 + jj;
        float s = sWb[768 + j];
#pragma unroll
        for (int c = 0; c < 48; c++)
            s = fmaf(sA[c * 64 + px], sWb[j * 48 + c], s);
        sI[(2 + j) * 64 + px] = fmaf(s, cat_scale[2 + j], cat_shift[2 + j]);
    }
    if (q == 0) {
        sI[px]      = fmaf((float)pxx * 0.125f, cat_scale[0], cat_shift[0]);
        sI[64 + px] = fmaf((float)py  * 0.125f, cat_scale[1], cat_shift[1]);
    }
    __syncthreads();

#pragma unroll
    for (int jj = 0; jj < 4; jj++) {
        int o = q * 4 + jj;
        float s = sP[288 + o];
#pragma unroll
        for (int c = 0; c < 18; c++)
            s = fmaf(sP[o * 18 + c], sI[c * 64 + px], s);
        sH0[o * 64 + px] = fmaxf(s, 0.f);
    }
    __syncthreads();

#pragma unroll
    for (int jj = 0; jj < 4; jj++) {
        int o = q * 4 + jj;
        float s = sP[560 + o];
#pragma unroll
        for (int c = 0; c < 16; c++)
            s = fmaf(sP[304 + o * 16 + c], sH0[c * 64 + px], s);
        sH1[o * 64 + px] = fmaxf(s, 0.f);
    }
    __syncthreads();

    float hr[16];
#pragma unroll
    for (int c = 0; c < 16; c++) hr[c] = sH1[c * 64 + px];
    const int y = ly * 8 + py, x = lx * 8 + pxx;
    float* ob = out + (((size_t)b * 256) << 14) + (y << 7) + x;
#pragma unroll 4
    for (int oo = 0; oo < 64; oo++) {
        int o = q * 64 + oo;
        float s = sP[4672 + o];
#pragma unroll
        for (int c = 0; c < 16; c++)
            s = fmaf(sP[576 + o * 16 + c], hr[c], s);
        ob[(size_t)o << 14] = s;
    }
}

// ---------------- host launcher ----------------
extern "C" void kernel_launch(void* const* d_in, const int* in_sizes, int n_in,
                              void* d_out, int out_size)
{
    const float* res5 = (const float*)d_in[0];
    const float* res2 = (const float*)d_in[1];
    const float* bw   = (const float*)d_in[2];
    const float* bn1s = (const float*)d_in[3];
    const float* bn1h = (const float*)d_in[4];
    const float* c0w  = (const float*)d_in[5];
    const float* bn2s = (const float*)d_in[6];
    const float* bn2h = (const float*)d_in[7];
    const float* c1w  = (const float*)d_in[8];
    const float* c1b  = (const float*)d_in[9];
    const float* aw   = (const float*)d_in[10];
    const float* bn3s = (const float*)d_in[11];
    const float* bn3h = (const float*)d_in[12];
    const float* bw2  = (const float*)d_in[13];
    const float* bb2  = (const float*)d_in[14];
    const float* cats = (const float*)d_in[15];
    const float* cath = (const float*)d_in[16];
    float* out = (float*)d_out;

    float *xcat, *x2, *cls1T, *c1a;
    cudaGetSymbolAddress((void**)&xcat,  g_xcat);
    cudaGetSymbolAddress((void**)&x2,    g_x2);
    cudaGetSymbolAddress((void**)&cls1T, g_cls1T);
    cudaGetSymbolAddress((void**)&c1a,   g_c1a);

    conv3x3_v2<2048><<<dim3(32, BATCH), 256>>>(res5, bw, bn1s, bn1h, xcat, 1024);
    gp_kernel<<<dim3(512, BATCH), 256>>>();
    conv3x3_v2<1024><<<dim3(64, BATCH), 256>>>(xcat, c0w, bn2s, bn2h, x2, 1024);
    cls1_v2<<<dim3(77, BATCH), 256>>>(x2, c1w, c1b, cls1T);
    c1a_v2<<<dim3(64, BATCH), 256>>>(res2, aw, bn3s, bn3h, c1a);
    fused_final<<<dim3(256, BATCH), 256>>>(cls1T, c1a, bw2, bb2, cats, cath, out);
}